// round 2
// baseline (speedup 1.0000x reference)
#include <cuda_runtime.h>
#include <math.h>

#define BATCH 2048
#define CLASSES 128
#define FEAT 1024

#define BM 64
#define BN 64
#define BK 16

// Scratch: softmax(weight) stored transposed: g_St[f][c]
__device__ float g_St[FEAT][CLASSES];

// ---------------------------------------------------------------------------
// Kernel 1: per-class softmax of weight rows, written transposed.
// grid = CLASSES blocks, 256 threads.
// ---------------------------------------------------------------------------
__global__ void softmax_w_kernel(const float* __restrict__ w) {
    const int c = blockIdx.x;
    const float* row = w + c * FEAT;
    __shared__ float red[256];
    const int tid = threadIdx.x;

    float m = -INFINITY;
    for (int f = tid; f < FEAT; f += 256) m = fmaxf(m, row[f]);
    red[tid] = m;
    __syncthreads();
    for (int s = 128; s > 0; s >>= 1) {
        if (tid < s) red[tid] = fmaxf(red[tid], red[tid + s]);
        __syncthreads();
    }
    m = red[0];
    __syncthreads();

    float sum = 0.0f;
    for (int f = tid; f < FEAT; f += 256) sum += expf(row[f] - m);
    red[tid] = sum;
    __syncthreads();
    for (int s = 128; s > 0; s >>= 1) {
        if (tid < s) red[tid] += red[tid + s];
        __syncthreads();
    }
    const float inv = 1.0f / red[0];

    for (int f = tid; f < FEAT; f += 256)
        g_St[f][c] = expf(row[f] - m) * inv;
}

// ---------------------------------------------------------------------------
// Kernel 2: out[b,c] = log( sum_f exp(x[b,f]) * St[f][c] )
// Tiled sgemm: BM=64, BN=64, BK=16, 256 threads, 4x4 micro-tile per thread.
// exp fused on A-load, log fused on epilogue.
// grid = (BATCH/BM, CLASSES/BN) = (32, 2)
// ---------------------------------------------------------------------------
__global__ void lse_gemm_kernel(const float* __restrict__ x,
                                float* __restrict__ out) {
    __shared__ float As[BK][BM];   // [k][m], exp() already applied
    __shared__ float Bs[BK][BN];   // [k][n]

    const int tid = threadIdx.x;
    const int bm = blockIdx.x * BM;
    const int bn = blockIdx.y * BN;
    const int tx = tid & 15;       // 0..15 -> n direction
    const int ty = tid >> 4;       // 0..15 -> m direction

    // A-load mapping: 64 rows x 16 k  = 1024 floats, float4 along K
    const int a_row = tid >> 2;          // 0..63
    const int a_kc  = (tid & 3) * 4;     // 0,4,8,12
    // B-load mapping: 16 k-rows x 64 n = 1024 floats, float4 along N
    const int b_row = tid >> 4;          // 0..15
    const int b_col = (tid & 15) * 4;    // 0..60

    const float* xp = x + (size_t)(bm + a_row) * FEAT;

    float acc[4][4] = {};

    for (int k0 = 0; k0 < FEAT; k0 += BK) {
        float4 av = *(const float4*)(xp + k0 + a_kc);
        As[a_kc + 0][a_row] = __expf(av.x);
        As[a_kc + 1][a_row] = __expf(av.y);
        As[a_kc + 2][a_row] = __expf(av.z);
        As[a_kc + 3][a_row] = __expf(av.w);

        *(float4*)(&Bs[b_row][b_col]) =
            *(const float4*)(&g_St[k0 + b_row][bn + b_col]);

        __syncthreads();

        #pragma unroll
        for (int k = 0; k < BK; k++) {
            float4 a4 = *(const float4*)(&As[k][ty * 4]);
            float4 b4 = *(const float4*)(&Bs[k][tx * 4]);
            float ar[4] = {a4.x, a4.y, a4.z, a4.w};
            float br[4] = {b4.x, b4.y, b4.z, b4.w};
            #pragma unroll
            for (int i = 0; i < 4; i++)
                #pragma unroll
                for (int j = 0; j < 4; j++)
                    acc[i][j] = fmaf(ar[i], br[j], acc[i][j]);
        }
        __syncthreads();
    }

    #pragma unroll
    for (int i = 0; i < 4; i++) {
        const int r = bm + ty * 4 + i;
        #pragma unroll
        for (int j = 0; j < 4; j++)
            out[(size_t)r * CLASSES + bn + tx * 4 + j] = logf(acc[i][j]);
    }
}

// ---------------------------------------------------------------------------
extern "C" void kernel_launch(void* const* d_in, const int* in_sizes, int n_in,
                              void* d_out, int out_size) {
    // Inputs per metadata: x (2048*16*64 f32), weight (128*1024 f32).
    // Be defensive about ordering via element counts.
    const float* x = (const float*)d_in[0];
    const float* w = (const float*)d_in[1];
    if (in_sizes[0] == CLASSES * FEAT && in_sizes[1] == BATCH * FEAT) {
        w = (const float*)d_in[0];
        x = (const float*)d_in[1];
    }
    float* out = (float*)d_out;

    softmax_w_kernel<<<CLASSES, 256>>>(w);
    dim3 grid(BATCH / BM, CLASSES / BN);
    lse_gemm_kernel<<<grid, 256>>>(x, out);
}

// round 3
// speedup vs baseline: 1.7377x; 1.7377x over previous
#include <cuda_runtime.h>
#include <math.h>
#include <stdint.h>

#define BATCH   2048
#define CLASSES 128
#define FEAT    1024

#define BM 64
#define BN 32
#define BK 32
#define NTILES (FEAT / BK)
#define ASTRIDE 36   // BK + 4: keeps float4 STS 16B-aligned and conflict-free

// Scratch: softmax(weight) stored transposed: g_St[f][c]
__device__ float g_St[FEAT][CLASSES];

// ---------------------------------------------------------------------------
// packed f32x2 helpers
// ---------------------------------------------------------------------------
__device__ __forceinline__ unsigned long long fma2(unsigned long long a,
                                                   unsigned long long b,
                                                   unsigned long long c) {
    unsigned long long d;
    asm("fma.rn.f32x2 %0, %1, %2, %3;" : "=l"(d) : "l"(a), "l"(b), "l"(c));
    return d;
}
__device__ __forceinline__ unsigned long long pack2(float lo, float hi) {
    unsigned long long r;
    asm("mov.b64 %0, {%1, %2};" : "=l"(r) : "f"(lo), "f"(hi));
    return r;
}
__device__ __forceinline__ void unpack2(unsigned long long v, float& lo, float& hi) {
    asm("mov.b64 {%0, %1}, %2;" : "=f"(lo), "=f"(hi) : "l"(v));
}

// ---------------------------------------------------------------------------
// Kernel 1: per-class softmax of weight rows, written transposed.
// ---------------------------------------------------------------------------
__global__ void softmax_w_kernel(const float* __restrict__ w) {
    const int c = blockIdx.x;
    const float* row = w + c * FEAT;
    __shared__ float red[256];
    const int tid = threadIdx.x;

    float m = -INFINITY;
    for (int f = tid; f < FEAT; f += 256) m = fmaxf(m, row[f]);
    red[tid] = m;
    __syncthreads();
    for (int s = 128; s > 0; s >>= 1) {
        if (tid < s) red[tid] = fmaxf(red[tid], red[tid + s]);
        __syncthreads();
    }
    m = red[0];
    __syncthreads();

    float sum = 0.0f;
    for (int f = tid; f < FEAT; f += 256) sum += expf(row[f] - m);
    red[tid] = sum;
    __syncthreads();
    for (int s = 128; s > 0; s >>= 1) {
        if (tid < s) red[tid] += red[tid + s];
        __syncthreads();
    }
    const float inv = 1.0f / red[0];

    for (int f = tid; f < FEAT; f += 256)
        g_St[f][c] = expf(row[f] - m) * inv;
}

// ---------------------------------------------------------------------------
// Kernel 2: out[b,c] = log( sum_f exp(x[b,f]) * St[f][c] )
// BM=64, BN=32, BK=32, 256 threads, 2x4 micro-tile, f32x2 FMA,
// double-buffered smem, one syncthreads per tile.
// grid = (32, 4) = 128 blocks
// ---------------------------------------------------------------------------
__global__ __launch_bounds__(256, 1)
void lse_gemm_kernel(const float* __restrict__ x, float* __restrict__ out) {
    __shared__ float As[2][BM][ASTRIDE];  // [m][k], exp() applied
    __shared__ float Bs[2][BK][BN];       // [k][n]

    const int tid = threadIdx.x;
    const int bm = blockIdx.x * BM;
    const int bn = blockIdx.y * BN;

    const int tx = tid & 7;    // n = tx*4 .. +3
    const int ty = tid >> 3;   // m = ty*2 .. +1

    // A-load: 64 rows x 32 k = 2048 floats -> 8/thread (2 float4 along k)
    const int a_row = tid >> 2;          // 0..63
    const int a_kc  = (tid & 3) * 8;     // 0,8,16,24
    // B-load: 32 k x 32 n = 1024 floats -> 4/thread (1 float4 along n)
    const int b_kr  = tid >> 3;          // 0..31
    const int b_nc  = (tid & 7) * 4;     // 0..28

    const float* xp = x + (size_t)(bm + a_row) * FEAT + a_kc;

    unsigned long long acc[2][2];
    acc[0][0] = acc[0][1] = acc[1][0] = acc[1][1] = 0ULL;

    // --- prologue: load tile 0 ---
    float4 ga0 = *(const float4*)(xp);
    float4 ga1 = *(const float4*)(xp + 4);
    float4 gb  = *(const float4*)(&g_St[b_kr][bn + b_nc]);

    {
        float* ap = &As[0][a_row][a_kc];
        ap[0] = __expf(ga0.x); ap[1] = __expf(ga0.y);
        ap[2] = __expf(ga0.z); ap[3] = __expf(ga0.w);
        ap[4] = __expf(ga1.x); ap[5] = __expf(ga1.y);
        ap[6] = __expf(ga1.z); ap[7] = __expf(ga1.w);
        *(float4*)(&Bs[0][b_kr][b_nc]) = gb;
    }
    __syncthreads();

    for (int t = 0; t < NTILES; t++) {
        const int buf = t & 1;

        // prefetch next tile from global (overlaps with compute below)
        if (t + 1 < NTILES) {
            const int k0n = (t + 1) * BK;
            ga0 = *(const float4*)(xp + k0n);
            ga1 = *(const float4*)(xp + k0n + 4);
            gb  = *(const float4*)(&g_St[k0n + b_kr][bn + b_nc]);
        }

        // compute on current buffer
        const float* arow0 = &As[buf][ty * 2][0];
        const float* arow1 = &As[buf][ty * 2 + 1][0];
        #pragma unroll
        for (int k = 0; k < BK; k++) {
            float a0 = arow0[k];
            float a1 = arow1[k];
            float4 bv = *(const float4*)(&Bs[buf][k][tx * 4]);
            unsigned long long aa0 = pack2(a0, a0);
            unsigned long long aa1 = pack2(a1, a1);
            unsigned long long b01 = pack2(bv.x, bv.y);
            unsigned long long b23 = pack2(bv.z, bv.w);
            acc[0][0] = fma2(aa0, b01, acc[0][0]);
            acc[0][1] = fma2(aa0, b23, acc[0][1]);
            acc[1][0] = fma2(aa1, b01, acc[1][0]);
            acc[1][1] = fma2(aa1, b23, acc[1][1]);
        }

        // store next tile into the other buffer
        if (t + 1 < NTILES) {
            const int nbuf = buf ^ 1;
            float* ap = &As[nbuf][a_row][a_kc];
            ap[0] = __expf(ga0.x); ap[1] = __expf(ga0.y);
            ap[2] = __expf(ga0.z); ap[3] = __expf(ga0.w);
            ap[4] = __expf(ga1.x); ap[5] = __expf(ga1.y);
            ap[6] = __expf(ga1.z); ap[7] = __expf(ga1.w);
            *(float4*)(&Bs[nbuf][b_kr][b_nc]) = gb;
            __syncthreads();
        }
    }

    // --- epilogue: log + store (2 rows x 4 cols, float4 each) ---
    #pragma unroll
    for (int i = 0; i < 2; i++) {
        float s0, s1, s2, s3;
        unpack2(acc[i][0], s0, s1);
        unpack2(acc[i][1], s2, s3);
        float4 o;
        o.x = logf(s0); o.y = logf(s1); o.z = logf(s2); o.w = logf(s3);
        const int r = bm + ty * 2 + i;
        *(float4*)(&out[(size_t)r * CLASSES + bn + tx * 4]) = o;
    }
}

// ---------------------------------------------------------------------------
extern "C" void kernel_launch(void* const* d_in, const int* in_sizes, int n_in,
                              void* d_out, int out_size) {
    const float* x = (const float*)d_in[0];
    const float* w = (const float*)d_in[1];
    if (in_sizes[0] == CLASSES * FEAT && in_sizes[1] == BATCH * FEAT) {
        w = (const float*)d_in[0];
        x = (const float*)d_in[1];
    }
    float* out = (float*)d_out;

    softmax_w_kernel<<<CLASSES, 256>>>(w);
    dim3 grid(BATCH / BM, CLASSES / BN);
    lse_gemm_kernel<<<grid, 256>>>(x, out);
}

// round 4
// speedup vs baseline: 2.1829x; 1.2562x over previous
#include <cuda_runtime.h>
#include <math.h>
#include <stdint.h>

#define BATCH   2048
#define CLASSES 128
#define FEAT    1024

#define BM 64
#define BN 64
#define BK 32
#define SPLITK 8
#define KSLICE (FEAT / SPLITK)          // 128
#define KTILES (KSLICE / BK)            // 4
#define ASTR (BM + 4)                   // 68: 16B-aligned rows, low conflict
#define BSTR (BN + 4)                   // 68

// softmax(weight) transposed: g_St[f][c]
__device__ float g_St[FEAT][CLASSES];
// split-K partials
__device__ float g_part[SPLITK][BATCH][CLASSES];

// ---------------------------------------------------------------------------
__device__ __forceinline__ unsigned long long fma2(unsigned long long a,
                                                   unsigned long long b,
                                                   unsigned long long c) {
    unsigned long long d;
    asm("fma.rn.f32x2 %0, %1, %2, %3;" : "=l"(d) : "l"(a), "l"(b), "l"(c));
    return d;
}
__device__ __forceinline__ unsigned long long pack2(float lo, float hi) {
    unsigned long long r;
    asm("mov.b64 %0, {%1, %2};" : "=l"(r) : "f"(lo), "f"(hi));
    return r;
}
__device__ __forceinline__ void unpack2(unsigned long long v, float& lo, float& hi) {
    asm("mov.b64 {%0, %1}, %2;" : "=f"(lo), "=f"(hi) : "l"(v));
}

// ---------------------------------------------------------------------------
// Kernel 1: per-class softmax of weight rows, written transposed.
// ---------------------------------------------------------------------------
__global__ void softmax_w_kernel(const float* __restrict__ w) {
    const int c = blockIdx.x;
    const float* row = w + c * FEAT;
    __shared__ float red[256];
    const int tid = threadIdx.x;

    float m = -INFINITY;
    for (int f = tid; f < FEAT; f += 256) m = fmaxf(m, row[f]);
    red[tid] = m;
    __syncthreads();
    for (int s = 128; s > 0; s >>= 1) {
        if (tid < s) red[tid] = fmaxf(red[tid], red[tid + s]);
        __syncthreads();
    }
    m = red[0];
    __syncthreads();

    float sum = 0.0f;
    for (int f = tid; f < FEAT; f += 256) sum += expf(row[f] - m);
    red[tid] = sum;
    __syncthreads();
    for (int s = 128; s > 0; s >>= 1) {
        if (tid < s) red[tid] += red[tid + s];
        __syncthreads();
    }
    const float inv = 1.0f / red[0];

    for (int f = tid; f < FEAT; f += 256)
        g_St[f][c] = expf(row[f] - m) * inv;
}

// ---------------------------------------------------------------------------
// Kernel 2: split-K GEMM partials: part[s][b][c] = sum_{k in slice s} exp(x)*St
// BM=64,BN=64,BK=32, 256 thr, 4x4 micro-tile, f32x2 FMA, double-buffered.
// grid = (32, 2, 8)
// ---------------------------------------------------------------------------
__global__ __launch_bounds__(256, 3)
void lse_gemm_kernel(const float* __restrict__ x) {
    __shared__ float As[2][BK][ASTR];   // [k][m], exp() applied
    __shared__ float Bs[2][BK][BSTR];   // [k][n]

    const int tid = threadIdx.x;
    const int bm = blockIdx.x * BM;
    const int bn = blockIdx.y * BN;
    const int kbase = blockIdx.z * KSLICE;

    const int tx = tid & 15;        // n: tx*4
    const int ty = tid >> 4;        // m: ty*4

    // A-load: 64 m x 32 k = 2048 floats -> 8/thread (2 float4 along k)
    const int a_row = tid >> 2;            // 0..63
    const int a_k   = (tid & 3) * 8;       // 0,8,16,24
    // B-load: 32 k x 64 n = 2048 floats -> 8/thread (2 float4 along n)
    const int b_k   = tid >> 3;            // 0..31
    const int b_n   = (tid & 7) * 8;       // 0..56

    const float* xp = x + (size_t)(bm + a_row) * FEAT + kbase + a_k;

    unsigned long long acc[2][4];   // [m-pair][n], pair = (m0,m1) packed
    #pragma unroll
    for (int p = 0; p < 2; p++)
        #pragma unroll
        for (int n = 0; n < 4; n++) acc[p][n] = 0ULL;

    // prologue: tile 0
    float4 ga0 = *(const float4*)(xp);
    float4 ga1 = *(const float4*)(xp + 4);
    float4 gb0 = *(const float4*)(&g_St[kbase + b_k][bn + b_n]);
    float4 gb1 = *(const float4*)(&g_St[kbase + b_k][bn + b_n + 4]);
    {
        As[0][a_k + 0][a_row] = __expf(ga0.x);
        As[0][a_k + 1][a_row] = __expf(ga0.y);
        As[0][a_k + 2][a_row] = __expf(ga0.z);
        As[0][a_k + 3][a_row] = __expf(ga0.w);
        As[0][a_k + 4][a_row] = __expf(ga1.x);
        As[0][a_k + 5][a_row] = __expf(ga1.y);
        As[0][a_k + 6][a_row] = __expf(ga1.z);
        As[0][a_k + 7][a_row] = __expf(ga1.w);
        *(float4*)(&Bs[0][b_k][b_n])     = gb0;
        *(float4*)(&Bs[0][b_k][b_n + 4]) = gb1;
    }
    __syncthreads();

    #pragma unroll
    for (int t = 0; t < KTILES; t++) {
        const int buf = t & 1;

        if (t + 1 < KTILES) {
            const int kn = (t + 1) * BK;
            ga0 = *(const float4*)(xp + kn);
            ga1 = *(const float4*)(xp + kn + 4);
            gb0 = *(const float4*)(&g_St[kbase + kn + b_k][bn + b_n]);
            gb1 = *(const float4*)(&g_St[kbase + kn + b_k][bn + b_n + 4]);
        }

        #pragma unroll
        for (int k = 0; k < BK; k++) {
            float4 a4 = *(const float4*)(&As[buf][k][ty * 4]);
            float4 b4 = *(const float4*)(&Bs[buf][k][tx * 4]);
            unsigned long long ap0 = pack2(a4.x, a4.y);
            unsigned long long ap1 = pack2(a4.z, a4.w);
            unsigned long long bd0 = pack2(b4.x, b4.x);
            unsigned long long bd1 = pack2(b4.y, b4.y);
            unsigned long long bd2 = pack2(b4.z, b4.z);
            unsigned long long bd3 = pack2(b4.w, b4.w);
            acc[0][0] = fma2(ap0, bd0, acc[0][0]);
            acc[0][1] = fma2(ap0, bd1, acc[0][1]);
            acc[0][2] = fma2(ap0, bd2, acc[0][2]);
            acc[0][3] = fma2(ap0, bd3, acc[0][3]);
            acc[1][0] = fma2(ap1, bd0, acc[1][0]);
            acc[1][1] = fma2(ap1, bd1, acc[1][1]);
            acc[1][2] = fma2(ap1, bd2, acc[1][2]);
            acc[1][3] = fma2(ap1, bd3, acc[1][3]);
        }

        if (t + 1 < KTILES) {
            const int nbuf = buf ^ 1;
            __syncthreads();   // ensure everyone done reading buf^1's old data
            As[nbuf][a_k + 0][a_row] = __expf(ga0.x);
            As[nbuf][a_k + 1][a_row] = __expf(ga0.y);
            As[nbuf][a_k + 2][a_row] = __expf(ga0.z);
            As[nbuf][a_k + 3][a_row] = __expf(ga0.w);
            As[nbuf][a_k + 4][a_row] = __expf(ga1.x);
            As[nbuf][a_k + 5][a_row] = __expf(ga1.y);
            As[nbuf][a_k + 6][a_row] = __expf(ga1.z);
            As[nbuf][a_k + 7][a_row] = __expf(ga1.w);
            *(float4*)(&Bs[nbuf][b_k][b_n])     = gb0;
            *(float4*)(&Bs[nbuf][b_k][b_n + 4]) = gb1;
            __syncthreads();
        }
    }

    // epilogue: store 4x4 partials
    float* base = &g_part[blockIdx.z][0][0];
    #pragma unroll
    for (int i = 0; i < 4; i++) {
        const int p = i >> 1;
        float v0, v1, v2, v3, hi0, hi1, hi2, hi3;
        unpack2(acc[p][0], v0, hi0);
        unpack2(acc[p][1], v1, hi1);
        unpack2(acc[p][2], v2, hi2);
        unpack2(acc[p][3], v3, hi3);
        float4 o;
        if (i & 1) { o.x = hi0; o.y = hi1; o.z = hi2; o.w = hi3; }
        else       { o.x = v0;  o.y = v1;  o.z = v2;  o.w = v3;  }
        const int r = bm + ty * 4 + i;
        *(float4*)(&base[(size_t)r * CLASSES + bn + tx * 4]) = o;
    }
}

// ---------------------------------------------------------------------------
// Kernel 3: reduce split-K partials + log. 1024 blocks x 256 thr, 1 out each.
// ---------------------------------------------------------------------------
__global__ void reduce_log_kernel(float* __restrict__ out) {
    const int idx = blockIdx.x * 256 + threadIdx.x;   // 0 .. 262143
    const float* p = &g_part[0][0][0] + idx;
    float s = 0.0f;
    #pragma unroll
    for (int j = 0; j < SPLITK; j++)
        s += p[(size_t)j * BATCH * CLASSES];
    out[idx] = logf(s);
}

// ---------------------------------------------------------------------------
extern "C" void kernel_launch(void* const* d_in, const int* in_sizes, int n_in,
                              void* d_out, int out_size) {
    const float* x = (const float*)d_in[0];
    const float* w = (const float*)d_in[1];
    if (in_sizes[0] == CLASSES * FEAT && in_sizes[1] == BATCH * FEAT) {
        w = (const float*)d_in[0];
        x = (const float*)d_in[1];
    }
    float* out = (float*)d_out;

    softmax_w_kernel<<<CLASSES, 256>>>(w);
    dim3 grid(BATCH / BM, CLASSES / BN, SPLITK);
    lse_gemm_kernel<<<grid, 256>>>(x);
    reduce_log_kernel<<<(BATCH * CLASSES) / 256, 256>>>(out);
}

// round 5
// speedup vs baseline: 2.2843x; 1.0465x over previous
#include <cuda_runtime.h>
#include <math.h>
#include <stdint.h>

#define BATCH   2048
#define CLASSES 128
#define FEAT    1024

#define BM 64
#define BN 64
#define BK 32
#define SPLITK 8
#define KSLICE (FEAT / SPLITK)          // 128
#define KTILES (KSLICE / BK)            // 4
#define ASTR (BM + 4)                   // 68
#define BSTR (BN + 4)                   // 68

// softmax(weight) transposed: g_St[f][c]
__device__ float g_St[FEAT][CLASSES];
// split-K partials
__device__ float g_part[SPLITK][BATCH][CLASSES];

// ---------------------------------------------------------------------------
__device__ __forceinline__ unsigned long long fma2(unsigned long long a,
                                                   unsigned long long b,
                                                   unsigned long long c) {
    unsigned long long d;
    asm("fma.rn.f32x2 %0, %1, %2, %3;" : "=l"(d) : "l"(a), "l"(b), "l"(c));
    return d;
}
__device__ __forceinline__ unsigned long long pack2(float lo, float hi) {
    unsigned long long r;
    asm("mov.b64 %0, {%1, %2};" : "=l"(r) : "f"(lo), "f"(hi));
    return r;
}
__device__ __forceinline__ void unpack2(unsigned long long v, float& lo, float& hi) {
    asm("mov.b64 {%0, %1}, %2;" : "=f"(lo), "=f"(hi) : "l"(v));
}

// ---------------------------------------------------------------------------
// Kernel 1: single-pass softmax of weight rows, written transposed.
// No max-subtraction needed: |w| <= ~0.7 (0.1*N(0,1)), exp can't overflow.
// grid = 128 (one class per block), 256 threads, 4 elems/thread in registers.
// ---------------------------------------------------------------------------
__global__ __launch_bounds__(256)
void softmax_w_kernel(const float* __restrict__ w) {
    const int c = blockIdx.x;
    const int tid = threadIdx.x;
    __shared__ float warp_sums[8];

    // one float4 per thread: f = tid*4 .. +3
    float4 v = *(const float4*)(w + (size_t)c * FEAT + tid * 4);
    float e0 = __expf(v.x), e1 = __expf(v.y), e2 = __expf(v.z), e3 = __expf(v.w);

    float s = (e0 + e1) + (e2 + e3);
    #pragma unroll
    for (int o = 16; o > 0; o >>= 1)
        s += __shfl_xor_sync(0xffffffffu, s, o);
    if ((tid & 31) == 0) warp_sums[tid >> 5] = s;
    __syncthreads();
    if (tid < 32) {
        float t = (tid < 8) ? warp_sums[tid] : 0.0f;
        #pragma unroll
        for (int o = 4; o > 0; o >>= 1)
            t += __shfl_xor_sync(0xffffffffu, t, o);
        if (tid == 0) warp_sums[0] = 1.0f / t;
    }
    __syncthreads();
    const float inv = warp_sums[0];

    const int f = tid * 4;
    g_St[f + 0][c] = e0 * inv;
    g_St[f + 1][c] = e1 * inv;
    g_St[f + 2][c] = e2 * inv;
    g_St[f + 3][c] = e3 * inv;
}

// ---------------------------------------------------------------------------
// Kernel 2: split-K GEMM partials (unchanged from R4 winner).
// ---------------------------------------------------------------------------
__global__ __launch_bounds__(256, 3)
void lse_gemm_kernel(const float* __restrict__ x) {
    __shared__ float As[2][BK][ASTR];   // [k][m], exp() applied
    __shared__ float Bs[2][BK][BSTR];   // [k][n]

    const int tid = threadIdx.x;
    const int bm = blockIdx.x * BM;
    const int bn = blockIdx.y * BN;
    const int kbase = blockIdx.z * KSLICE;

    const int tx = tid & 15;        // n: tx*4
    const int ty = tid >> 4;        // m: ty*4

    const int a_row = tid >> 2;            // 0..63
    const int a_k   = (tid & 3) * 8;       // 0,8,16,24
    const int b_k   = tid >> 3;            // 0..31
    const int b_n   = (tid & 7) * 8;       // 0..56

    const float* xp = x + (size_t)(bm + a_row) * FEAT + kbase + a_k;

    unsigned long long acc[2][4];
    #pragma unroll
    for (int p = 0; p < 2; p++)
        #pragma unroll
        for (int n = 0; n < 4; n++) acc[p][n] = 0ULL;

    float4 ga0 = *(const float4*)(xp);
    float4 ga1 = *(const float4*)(xp + 4);
    float4 gb0 = *(const float4*)(&g_St[kbase + b_k][bn + b_n]);
    float4 gb1 = *(const float4*)(&g_St[kbase + b_k][bn + b_n + 4]);
    {
        As[0][a_k + 0][a_row] = __expf(ga0.x);
        As[0][a_k + 1][a_row] = __expf(ga0.y);
        As[0][a_k + 2][a_row] = __expf(ga0.z);
        As[0][a_k + 3][a_row] = __expf(ga0.w);
        As[0][a_k + 4][a_row] = __expf(ga1.x);
        As[0][a_k + 5][a_row] = __expf(ga1.y);
        As[0][a_k + 6][a_row] = __expf(ga1.z);
        As[0][a_k + 7][a_row] = __expf(ga1.w);
        *(float4*)(&Bs[0][b_k][b_n])     = gb0;
        *(float4*)(&Bs[0][b_k][b_n + 4]) = gb1;
    }
    __syncthreads();

    #pragma unroll
    for (int t = 0; t < KTILES; t++) {
        const int buf = t & 1;

        if (t + 1 < KTILES) {
            const int kn = (t + 1) * BK;
            ga0 = *(const float4*)(xp + kn);
            ga1 = *(const float4*)(xp + kn + 4);
            gb0 = *(const float4*)(&g_St[kbase + kn + b_k][bn + b_n]);
            gb1 = *(const float4*)(&g_St[kbase + kn + b_k][bn + b_n + 4]);
        }

        #pragma unroll
        for (int k = 0; k < BK; k++) {
            float4 a4 = *(const float4*)(&As[buf][k][ty * 4]);
            float4 b4 = *(const float4*)(&Bs[buf][k][tx * 4]);
            unsigned long long ap0 = pack2(a4.x, a4.y);
            unsigned long long ap1 = pack2(a4.z, a4.w);
            unsigned long long bd0 = pack2(b4.x, b4.x);
            unsigned long long bd1 = pack2(b4.y, b4.y);
            unsigned long long bd2 = pack2(b4.z, b4.z);
            unsigned long long bd3 = pack2(b4.w, b4.w);
            acc[0][0] = fma2(ap0, bd0, acc[0][0]);
            acc[0][1] = fma2(ap0, bd1, acc[0][1]);
            acc[0][2] = fma2(ap0, bd2, acc[0][2]);
            acc[0][3] = fma2(ap0, bd3, acc[0][3]);
            acc[1][0] = fma2(ap1, bd0, acc[1][0]);
            acc[1][1] = fma2(ap1, bd1, acc[1][1]);
            acc[1][2] = fma2(ap1, bd2, acc[1][2]);
            acc[1][3] = fma2(ap1, bd3, acc[1][3]);
        }

        if (t + 1 < KTILES) {
            const int nbuf = buf ^ 1;
            __syncthreads();
            As[nbuf][a_k + 0][a_row] = __expf(ga0.x);
            As[nbuf][a_k + 1][a_row] = __expf(ga0.y);
            As[nbuf][a_k + 2][a_row] = __expf(ga0.z);
            As[nbuf][a_k + 3][a_row] = __expf(ga0.w);
            As[nbuf][a_k + 4][a_row] = __expf(ga1.x);
            As[nbuf][a_k + 5][a_row] = __expf(ga1.y);
            As[nbuf][a_k + 6][a_row] = __expf(ga1.z);
            As[nbuf][a_k + 7][a_row] = __expf(ga1.w);
            *(float4*)(&Bs[nbuf][b_k][b_n])     = gb0;
            *(float4*)(&Bs[nbuf][b_k][b_n + 4]) = gb1;
            __syncthreads();
        }
    }

    float* base = &g_part[blockIdx.z][0][0];
    #pragma unroll
    for (int i = 0; i < 4; i++) {
        const int p = i >> 1;
        float v0, v1, v2, v3, hi0, hi1, hi2, hi3;
        unpack2(acc[p][0], v0, hi0);
        unpack2(acc[p][1], v1, hi1);
        unpack2(acc[p][2], v2, hi2);
        unpack2(acc[p][3], v3, hi3);
        float4 o;
        if (i & 1) { o.x = hi0; o.y = hi1; o.z = hi2; o.w = hi3; }
        else       { o.x = v0;  o.y = v1;  o.z = v2;  o.w = v3;  }
        const int r = bm + ty * 4 + i;
        *(float4*)(&base[(size_t)r * CLASSES + bn + tx * 4]) = o;
    }
}

// ---------------------------------------------------------------------------
// Kernel 3: reduce split-K partials + log. float4-vectorized.
// 256 blocks x 256 thr, 4 outputs each.
// ---------------------------------------------------------------------------
__global__ __launch_bounds__(256)
void reduce_log_kernel(float* __restrict__ out) {
    const int idx4 = blockIdx.x * 256 + threadIdx.x;   // 0 .. 65535
    const float4* p = (const float4*)(&g_part[0][0][0]) + idx4;
    float4 s = p[0];
    #pragma unroll
    for (int j = 1; j < SPLITK; j++) {
        float4 v = p[(size_t)j * (BATCH * CLASSES / 4)];
        s.x += v.x; s.y += v.y; s.z += v.z; s.w += v.w;
    }
    float4 o;
    o.x = __logf(s.x); o.y = __logf(s.y); o.z = __logf(s.z); o.w = __logf(s.w);
    ((float4*)out)[idx4] = o;
}

// ---------------------------------------------------------------------------
extern "C" void kernel_launch(void* const* d_in, const int* in_sizes, int n_in,
                              void* d_out, int out_size) {
    const float* x = (const float*)d_in[0];
    const float* w = (const float*)d_in[1];
    if (in_sizes[0] == CLASSES * FEAT && in_sizes[1] == BATCH * FEAT) {
        w = (const float*)d_in[0];
        x = (const float*)d_in[1];
    }
    float* out = (float*)d_out;

    softmax_w_kernel<<<CLASSES, 256>>>(w);
    dim3 grid(BATCH / BM, CLASSES / BN, SPLITK);
    lse_gemm_kernel<<<grid, 256>>>(x);
    reduce_log_kernel<<<(BATCH * CLASSES) / 4 / 256, 256>>>(out);
}

// round 6
// speedup vs baseline: 2.6781x; 1.1724x over previous
#include <cuda_runtime.h>
#include <math.h>
#include <stdint.h>

#define BATCH   2048
#define CLASSES 128
#define FEAT    1024

#define BM 128
#define BN 128
#define KS 64                       // k-slice per block
#define SPLITK (FEAT / KS)          // 16
#define SROW 132                    // padded row (132*4=528B, 16B-aligned)
#define SMEM_BYTES (2 * KS * SROW * 4)

// split-K partials and Z partials
__device__ float g_part[SPLITK][BATCH][CLASSES];
__device__ float g_zpart[SPLITK][CLASSES];

// ---------------------------------------------------------------------------
__device__ __forceinline__ unsigned long long fma2(unsigned long long a,
                                                   unsigned long long b,
                                                   unsigned long long c) {
    unsigned long long d;
    asm("fma.rn.f32x2 %0, %1, %2, %3;" : "=l"(d) : "l"(a), "l"(b), "l"(c));
    return d;
}
__device__ __forceinline__ unsigned long long pack2(float lo, float hi) {
    unsigned long long r;
    asm("mov.b64 %0, {%1, %2};" : "=l"(r) : "f"(lo), "f"(hi));
    return r;
}
__device__ __forceinline__ void unpack2(unsigned long long v, float& lo, float& hi) {
    asm("mov.b64 {%0, %1}, %2;" : "=f"(lo), "=f"(hi) : "l"(v));
}

// ---------------------------------------------------------------------------
// Fused GEMM: part[z][b][c] = sum_{k in slice z} exp(x[b,k]) * exp(w[c,k])
// B operand built from raw w inside the kernel (no softmax kernel needed).
// bx==0 blocks also emit zpart[z][c] = sum_k exp(w[c,k]).
// grid (16, 16) = (m-tiles, splitk). 256 threads, 8x8 micro-tile, f32x2 FMA.
// ---------------------------------------------------------------------------
__global__ __launch_bounds__(256, 2)
void lse_gemm_kernel(const float* __restrict__ x, const float* __restrict__ w) {
    extern __shared__ float smem[];
    float (*As)[SROW] = (float (*)[SROW])smem;             // [k][m], exp(x)
    float (*Bs)[SROW] = (float (*)[SROW])(smem + KS * SROW); // [k][n], exp(w)

    const int tid = threadIdx.x;
    const int bm = blockIdx.x * BM;
    const int kbase = blockIdx.y * KS;

    // ---- prologue: load + exp + transpose both operands into smem ----
    // per operand: thread t covers rows (t>>2) and (t>>2)+64,
    // float4 cols q = (t&3) + 4i  (i=0..3)  -> k0 = 4q
    {
        const int r0 = tid >> 2;
        const int qb = tid & 3;
        const float* ax = x + (size_t)(bm + r0) * FEAT + kbase;
        const float* bw = w + (size_t)r0 * FEAT + kbase;
        #pragma unroll
        for (int half = 0; half < 2; half++) {
            const int r = r0 + half * 64;
            const float* pa = ax + (size_t)half * 64 * FEAT;
            const float* pb = bw + (size_t)half * 64 * FEAT;
            #pragma unroll
            for (int i = 0; i < 4; i++) {
                const int k0 = (qb + 4 * i) * 4;
                float4 va = *(const float4*)(pa + k0);
                As[k0 + 0][r] = __expf(va.x);
                As[k0 + 1][r] = __expf(va.y);
                As[k0 + 2][r] = __expf(va.z);
                As[k0 + 3][r] = __expf(va.w);
                float4 vb = *(const float4*)(pb + k0);
                Bs[k0 + 0][r] = __expf(vb.x);
                Bs[k0 + 1][r] = __expf(vb.y);
                Bs[k0 + 2][r] = __expf(vb.z);
                Bs[k0 + 3][r] = __expf(vb.w);
            }
        }
    }
    __syncthreads();

    // ---- Z partials (only one m-block per slice; B tile identical) ----
    if (blockIdx.x == 0 && tid < CLASSES) {
        float s = 0.0f;
        #pragma unroll 16
        for (int k = 0; k < KS; k++) s += Bs[k][tid];
        g_zpart[blockIdx.y][tid] = s;
    }

    // ---- main compute: 8x8 per thread, acc pairs over n ----
    const int m0 = (tid >> 4) * 8;
    const int n0 = (tid & 15) * 8;

    unsigned long long acc[8][4];
    #pragma unroll
    for (int m = 0; m < 8; m++)
        #pragma unroll
        for (int p = 0; p < 4; p++) acc[m][p] = 0ULL;

    #pragma unroll 8
    for (int k = 0; k < KS; k++) {
        float4 a0 = *(const float4*)(&As[k][m0]);
        float4 a1 = *(const float4*)(&As[k][m0 + 4]);
        float4 b0 = *(const float4*)(&Bs[k][n0]);
        float4 b1 = *(const float4*)(&Bs[k][n0 + 4]);
        unsigned long long bp0 = pack2(b0.x, b0.y);
        unsigned long long bp1 = pack2(b0.z, b0.w);
        unsigned long long bp2 = pack2(b1.x, b1.y);
        unsigned long long bp3 = pack2(b1.z, b1.w);
        float am[8] = {a0.x, a0.y, a0.z, a0.w, a1.x, a1.y, a1.z, a1.w};
        #pragma unroll
        for (int m = 0; m < 8; m++) {
            unsigned long long ad = pack2(am[m], am[m]);
            acc[m][0] = fma2(ad, bp0, acc[m][0]);
            acc[m][1] = fma2(ad, bp1, acc[m][1]);
            acc[m][2] = fma2(ad, bp2, acc[m][2]);
            acc[m][3] = fma2(ad, bp3, acc[m][3]);
        }
    }

    // ---- epilogue: store 8x8 partials ----
    float* dst = &g_part[blockIdx.y][0][0];
    #pragma unroll
    for (int m = 0; m < 8; m++) {
        const size_t row = (size_t)(bm + m0 + m) * CLASSES;
        float4 o0, o1;
        unpack2(acc[m][0], o0.x, o0.y);
        unpack2(acc[m][1], o0.z, o0.w);
        unpack2(acc[m][2], o1.x, o1.y);
        unpack2(acc[m][3], o1.z, o1.w);
        *(float4*)(&dst[row + n0])     = o0;
        *(float4*)(&dst[row + n0 + 4]) = o1;
    }
}

// ---------------------------------------------------------------------------
// Reduce: out[b,c] = log( (sum_z part[z][b][c]) / Z[c] )
// 256 blocks x 256 thr, 4 outputs per thread (float4).
// ---------------------------------------------------------------------------
__global__ __launch_bounds__(256)
void reduce_log_kernel(float* __restrict__ out) {
    __shared__ float rZ[CLASSES];
    const int tid = threadIdx.x;

    if (tid < CLASSES) {
        float s = 0.0f;
        #pragma unroll
        for (int z = 0; z < SPLITK; z++) s += g_zpart[z][tid];
        rZ[tid] = 1.0f / s;
    }
    __syncthreads();

    const int idx4 = blockIdx.x * 256 + tid;          // 0 .. 65535
    const float4* p = (const float4*)(&g_part[0][0][0]) + idx4;
    float4 s = p[0];
    #pragma unroll
    for (int z = 1; z < SPLITK; z++) {
        float4 v = p[(size_t)z * (BATCH * CLASSES / 4)];
        s.x += v.x; s.y += v.y; s.z += v.z; s.w += v.w;
    }
    const int c0 = (idx4 * 4) & (CLASSES - 1);
    float4 o;
    o.x = __logf(s.x * rZ[c0 + 0]);
    o.y = __logf(s.y * rZ[c0 + 1]);
    o.z = __logf(s.z * rZ[c0 + 2]);
    o.w = __logf(s.w * rZ[c0 + 3]);
    ((float4*)out)[idx4] = o;
}

// ---------------------------------------------------------------------------
extern "C" void kernel_launch(void* const* d_in, const int* in_sizes, int n_in,
                              void* d_out, int out_size) {
    const float* x = (const float*)d_in[0];
    const float* w = (const float*)d_in[1];
    if (in_sizes[0] == CLASSES * FEAT && in_sizes[1] == BATCH * FEAT) {
        w = (const float*)d_in[0];
        x = (const float*)d_in[1];
    }
    float* out = (float*)d_out;

    cudaFuncSetAttribute(lse_gemm_kernel,
                         cudaFuncAttributeMaxDynamicSharedMemorySize, SMEM_BYTES);

    dim3 grid(BATCH / BM, SPLITK);
    lse_gemm_kernel<<<grid, 256, SMEM_BYTES>>>(x, w);
    reduce_log_kernel<<<(BATCH * CLASSES) / 4 / 256, 256>>>(out);
}